// round 1
// baseline (speedup 1.0000x reference)
#include <cuda_runtime.h>

// ---------------------------------------------------------------------------
// EuclideanCodebook: argmax_n ( 2 x·e_n - ||x||^2 - ||e_n||^2 ) over K=1024
// codes, d=128, N=131072 rows, then quantize = embed[ind].
// ||x||^2 is row-constant -> argmax of (x·e_n - 0.5||e_n||^2).
//
// Strategy: fp32 GEMM-like tiled kernel fused with row argmax, using packed
// fma.rn.f32x2 (FFMA2) to hit full sm_103a fp32 rate. Half-norms precomputed
// into __device__ scratch and folded into accumulator init.
// ---------------------------------------------------------------------------

#define BM 64
#define BN 128
#define XS_STRIDE 68            // 128 x 68 floats  (x tile, transposed [k][m])
#define ES_STRIDE 132           // 128 x 132 floats (e chunk, transposed [k][n])
#define SMEM_FLOATS (128 * XS_STRIDE + 128 * ES_STRIDE)

__device__ float g_hn[4096];    // 0.5 * ||e_c||^2 scratch (K <= 4096)

__device__ __forceinline__ unsigned long long pack2(float lo, float hi) {
    unsigned long long r;
    asm("mov.b64 %0, {%1, %2};" : "=l"(r) : "f"(lo), "f"(hi));
    return r;
}
__device__ __forceinline__ void unpack2(unsigned long long v, float& lo, float& hi) {
    asm("mov.b64 {%0, %1}, %2;" : "=f"(lo), "=f"(hi) : "l"(v));
}
__device__ __forceinline__ unsigned long long ffma2(
    unsigned long long a, unsigned long long b, unsigned long long c) {
    unsigned long long d;
    asm("fma.rn.f32x2 %0, %1, %2, %3;" : "=l"(d) : "l"(a), "l"(b), "l"(c));
    return d;
}

// ---------------------------------------------------------------------------
// Precompute 0.5 * ||e_c||^2
// ---------------------------------------------------------------------------
__global__ void hn_kernel(const float* __restrict__ embed, int K) {
    int c = blockIdx.x * blockDim.x + threadIdx.x;
    if (c < K) {
        const float4* e = (const float4*)(embed + (size_t)c * 128);
        float s = 0.f;
#pragma unroll
        for (int i = 0; i < 32; i++) {
            float4 v = e[i];
            s += v.x * v.x + v.y * v.y + v.z * v.z + v.w * v.w;
        }
        g_hn[c] = 0.5f * s;
    }
}

// ---------------------------------------------------------------------------
// Main fused GEMM + argmax + gather kernel.
// Block: 256 threads (16 tx = code dim, 16 ty = row dim).
// Each thread: 4 rows x 8 codes (as 4 f32x2 pairs) micro-tile.
// ---------------------------------------------------------------------------
__global__ __launch_bounds__(256, 2) void vq_kernel(
    const float* __restrict__ x, const float* __restrict__ embed,
    int N, int K, float* __restrict__ out_ind, float* __restrict__ out_q) {
    extern __shared__ float smem[];
    float* Xs = smem;                        // [128][XS_STRIDE]
    float* Es = smem + 128 * XS_STRIDE;      // [128][ES_STRIDE]

    const int tx = threadIdx.x;              // 0..15 : codes
    const int ty = threadIdx.y;              // 0..15 : rows
    const int t  = ty * 16 + tx;
    const int rowBase = blockIdx.x * BM;

    // ---- load X tile (64 rows x 128 dims), transposed into Xs[k][m] ----
    {
        int r  = t >> 2;                     // 0..63 local row
        int kb = (t & 3) * 32;               // dim base for this thread
        int gr = rowBase + r;
        if (gr >= N) gr = N - 1;             // clamp (writes are guarded later)
        const float4* xr = (const float4*)(x + (size_t)gr * 128 + kb);
#pragma unroll
        for (int i = 0; i < 8; i++) {
            float4 v = xr[i];
            int k = kb + i * 4;
            Xs[(k + 0) * XS_STRIDE + r] = v.x;
            Xs[(k + 1) * XS_STRIDE + r] = v.y;
            Xs[(k + 2) * XS_STRIDE + r] = v.z;
            Xs[(k + 3) * XS_STRIDE + r] = v.w;
        }
    }

    float gbv[4];
    int   gbi[4];
#pragma unroll
    for (int r = 0; r < 4; r++) { gbv[r] = -3.4e38f; gbi[r] = 0; }

    for (int cb = 0; cb < K; cb += BN) {
        __syncthreads();                     // protect Es from overwrite
        // ---- load E chunk (128 codes x 128 dims), transposed Es[k][n] ----
        {
            int c  = t >> 1;                 // 0..127 local code
            int kb = (t & 1) * 64;
            int gc = cb + c;
            if (gc >= K) gc = K - 1;
            const float4* er = (const float4*)(embed + (size_t)gc * 128 + kb);
#pragma unroll
            for (int i = 0; i < 16; i++) {
                float4 v = er[i];
                int k = kb + i * 4;
                Es[(k + 0) * ES_STRIDE + c] = v.x;
                Es[(k + 1) * ES_STRIDE + c] = v.y;
                Es[(k + 2) * ES_STRIDE + c] = v.z;
                Es[(k + 3) * ES_STRIDE + c] = v.w;
            }
        }
        __syncthreads();

        const int c0 = cb + tx * 8;

        // init accumulators to -0.5||e||^2 (folds the norm term for free)
        unsigned long long acc[4][4];
#pragma unroll
        for (int p = 0; p < 4; p++) {
            unsigned long long init = pack2(-g_hn[c0 + 2 * p], -g_hn[c0 + 2 * p + 1]);
            acc[0][p] = init; acc[1][p] = init; acc[2][p] = init; acc[3][p] = init;
        }

        const float* xp = Xs + ty * 4;
        const float* ep = Es + tx * 8;
#pragma unroll 8
        for (int k = 0; k < 128; k++) {
            float4 a = *(const float4*)(xp + k * XS_STRIDE);
            // 8 contiguous codes at dim k -> two 16B loads, already f32x2-packed
            ulonglong2 B0 = *(const ulonglong2*)(ep + k * ES_STRIDE);
            ulonglong2 B1 = *(const ulonglong2*)(ep + k * ES_STRIDE + 4);
            unsigned long long a0 = pack2(a.x, a.x);
            unsigned long long a1 = pack2(a.y, a.y);
            unsigned long long a2 = pack2(a.z, a.z);
            unsigned long long a3 = pack2(a.w, a.w);
            acc[0][0] = ffma2(a0, B0.x, acc[0][0]);
            acc[0][1] = ffma2(a0, B0.y, acc[0][1]);
            acc[0][2] = ffma2(a0, B1.x, acc[0][2]);
            acc[0][3] = ffma2(a0, B1.y, acc[0][3]);
            acc[1][0] = ffma2(a1, B0.x, acc[1][0]);
            acc[1][1] = ffma2(a1, B0.y, acc[1][1]);
            acc[1][2] = ffma2(a1, B1.x, acc[1][2]);
            acc[1][3] = ffma2(a1, B1.y, acc[1][3]);
            acc[2][0] = ffma2(a2, B0.x, acc[2][0]);
            acc[2][1] = ffma2(a2, B0.y, acc[2][1]);
            acc[2][2] = ffma2(a2, B1.x, acc[2][2]);
            acc[2][3] = ffma2(a2, B1.y, acc[2][3]);
            acc[3][0] = ffma2(a3, B0.x, acc[3][0]);
            acc[3][1] = ffma2(a3, B0.y, acc[3][1]);
            acc[3][2] = ffma2(a3, B1.x, acc[3][2]);
            acc[3][3] = ffma2(a3, B1.y, acc[3][3]);
        }

        // ---- per-chunk argmax (first-max tie-break, matching jnp.argmax) ----
#pragma unroll
        for (int r = 0; r < 4; r++) {
            float bv = -3.4e38f;
            int   bi = 0;
#pragma unroll
            for (int p = 0; p < 4; p++) {
                float v0, v1;
                unpack2(acc[r][p], v0, v1);
                if (v0 > bv) { bv = v0; bi = c0 + 2 * p; }
                if (v1 > bv) { bv = v1; bi = c0 + 2 * p + 1; }
            }
            // reduce across the 16 tx lanes sharing this row (same half-warp)
#pragma unroll
            for (int off = 8; off > 0; off >>= 1) {
                float ov = __shfl_xor_sync(0xffffffffu, bv, off);
                int   oi = __shfl_xor_sync(0xffffffffu, bi, off);
                if (ov > bv || (ov == bv && oi < bi)) { bv = ov; bi = oi; }
            }
            // strict > keeps earlier (lower-index) chunk winner on exact ties
            if (bv > gbv[r]) { gbv[r] = bv; gbi[r] = bi; }
        }
    }

    // ---- write indices + gather quantize rows ----
#pragma unroll
    for (int r = 0; r < 4; r++) {
        int row = rowBase + ty * 4 + r;
        if (row < N) {
            if (out_ind && tx == 0) out_ind[row] = (float)gbi[r];
            if (out_q) {
                const float4* src = (const float4*)(embed + (size_t)gbi[r] * 128);
                float4* dst = (float4*)(out_q + (size_t)row * 128);
                dst[tx * 2]     = src[tx * 2];
                dst[tx * 2 + 1] = src[tx * 2 + 1];
            }
        }
    }
}

// ---------------------------------------------------------------------------
extern "C" void kernel_launch(void* const* d_in, const int* in_sizes, int n_in,
                              void* d_out, int out_size) {
    const float* x     = (const float*)d_in[0];
    const float* embed = (const float*)d_in[1];
    const int N = in_sizes[0] / 128;   // 131072
    const int K = in_sizes[1] / 128;   // 1024

    float* out     = (float*)d_out;
    float* out_ind = out;              // default: [ind (N floats)][quantize (N*128)]
    float* out_q   = out + N;
    long long os = (long long)out_size;
    if (os == (long long)N * 128) { out_ind = nullptr; out_q = out; }
    else if (os == (long long)N) { out_q = nullptr; }

    hn_kernel<<<(K + 127) / 128, 128>>>(embed, K);

    cudaFuncSetAttribute(vq_kernel, cudaFuncAttributeMaxDynamicSharedMemorySize,
                         SMEM_FLOATS * 4);
    dim3 blk(16, 16);
    int grid = (N + BM - 1) / BM;
    vq_kernel<<<grid, blk, SMEM_FLOATS * 4>>>(x, embed, N, K, out_ind, out_q);
}

// round 2
// speedup vs baseline: 1.5632x; 1.5632x over previous
#include <cuda_runtime.h>

// ---------------------------------------------------------------------------
// EuclideanCodebook: argmax_c ( x·e_c - 0.5||e_c||^2 ) over K=1024 codes,
// d=128, N=131072 rows; then quantize = embed[ind].
//
// R2: 8x8 register micro-tile (128x128 block tile), X stored DUPLICATED in
// smem so LDS yields pre-packed f32x2 broadcast operands (no pack MOVs),
// e-tile ownership arranged for conflict-free LDS.128 (contiguous 16B/lane).
// Target: FMA-pipe bound (~478us floor for fp32 FFMA2 @72TF/s).
// ---------------------------------------------------------------------------

#define BM 128
#define BN 128
#define XS2_STRIDE 260          // 128 k-rows x (256 dup floats + pad)
#define ES_STRIDE  132          // 128 k-rows x (128 floats + pad)
#define SMEM_FLOATS (128 * XS2_STRIDE + 128 * ES_STRIDE)   // 50176 floats = 200704 B

__device__ float g_hn[4096];    // 0.5 * ||e_c||^2

__device__ __forceinline__ unsigned long long pack2(float lo, float hi) {
    unsigned long long r;
    asm("mov.b64 %0, {%1, %2};" : "=l"(r) : "f"(lo), "f"(hi));
    return r;
}
__device__ __forceinline__ void unpack2(unsigned long long v, float& lo, float& hi) {
    asm("mov.b64 {%0, %1}, %2;" : "=f"(lo), "=f"(hi) : "l"(v));
}
__device__ __forceinline__ unsigned long long ffma2(
    unsigned long long a, unsigned long long b, unsigned long long c) {
    unsigned long long d;
    asm("fma.rn.f32x2 %0, %1, %2, %3;" : "=l"(d) : "l"(a), "l"(b), "l"(c));
    return d;
}

// ---------------------------------------------------------------------------
__global__ void hn_kernel(const float* __restrict__ embed, int K) {
    int c = blockIdx.x * blockDim.x + threadIdx.x;
    if (c < K) {
        const float4* e = (const float4*)(embed + (size_t)c * 128);
        float s = 0.f;
#pragma unroll
        for (int i = 0; i < 32; i++) {
            float4 v = e[i];
            s += v.x * v.x + v.y * v.y + v.z * v.z + v.w * v.w;
        }
        g_hn[c] = 0.5f * s;
    }
}

// ---------------------------------------------------------------------------
// Block: 256 threads (16 tx = codes, 16 ty = rows). Tile 128 rows x 128 codes.
// Thread micro-tile: 8 rows x 8 codes (codes tx*4..+3 and 64+tx*4..+3).
// ---------------------------------------------------------------------------
__global__ __launch_bounds__(256, 1) void vq_kernel(
    const float* __restrict__ x, const float* __restrict__ embed,
    int N, int K, float* __restrict__ out_ind, float* __restrict__ out_q) {
    extern __shared__ float smem[];
    float* Xs2 = smem;                         // [128][XS2_STRIDE] duplicated
    float* Es  = smem + 128 * XS2_STRIDE;      // [128][ES_STRIDE]

    const int tx = threadIdx.x;                // 0..15 : codes
    const int ty = threadIdx.y;                // 0..15 : rows
    const int t  = ty * 16 + tx;
    const int rowBase = blockIdx.x * BM;

    // ---- load X tile (128 rows x 128 dims), transposed + DUPLICATED ----
    {
        int r  = t >> 1;                       // 0..127 local row
        int kb = (t & 1) * 64;                 // dim base
        int gr = rowBase + r;
        if (gr >= N) gr = N - 1;
        const float4* xr = (const float4*)(x + (size_t)gr * 128 + kb);
#pragma unroll
        for (int i = 0; i < 16; i++) {
            float4 v = xr[i];
            int k = kb + i * 4;
            *(float2*)(Xs2 + (k + 0) * XS2_STRIDE + 2 * r) = make_float2(v.x, v.x);
            *(float2*)(Xs2 + (k + 1) * XS2_STRIDE + 2 * r) = make_float2(v.y, v.y);
            *(float2*)(Xs2 + (k + 2) * XS2_STRIDE + 2 * r) = make_float2(v.z, v.z);
            *(float2*)(Xs2 + (k + 3) * XS2_STRIDE + 2 * r) = make_float2(v.w, v.w);
        }
    }

    float gbv[8];
    int   gbi[8];
#pragma unroll
    for (int r = 0; r < 8; r++) { gbv[r] = -3.4e38f; gbi[r] = 0; }

    for (int cb = 0; cb < K; cb += BN) {
        __syncthreads();                       // protect Es from overwrite
        // ---- load E chunk (128 codes x 128 dims), transposed Es[k][c] ----
        {
            int c  = t >> 1;                   // 0..127 local code
            int kb = (t & 1) * 64;
            int gc = cb + c;
            if (gc >= K) gc = K - 1;
            const float4* er = (const float4*)(embed + (size_t)gc * 128 + kb);
#pragma unroll
            for (int i = 0; i < 16; i++) {
                float4 v = er[i];
                int k = kb + i * 4;
                Es[(k + 0) * ES_STRIDE + c] = v.x;
                Es[(k + 1) * ES_STRIDE + c] = v.y;
                Es[(k + 2) * ES_STRIDE + c] = v.z;
                Es[(k + 3) * ES_STRIDE + c] = v.w;
            }
        }
        __syncthreads();

        const int c0a = cb + tx * 4;           // codes c0a..c0a+3 (acc p=0,1)
        const int c0b = cb + 64 + tx * 4;      // codes c0b..c0b+3 (acc p=2,3)

        unsigned long long acc[8][4];
#pragma unroll
        for (int r = 0; r < 8; r++)
#pragma unroll
            for (int p = 0; p < 4; p++) acc[r][p] = 0ull;

        const float* xp = Xs2 + ty * 16;       // 8 rows duplicated = 16 floats
        const float* ep = Es + tx * 4;
#pragma unroll 4
        for (int k = 0; k < 128; k++) {
            // 8 rows, pre-duplicated -> 4 x 16B loads, broadcast-friendly
            ulonglong2 A0 = *(const ulonglong2*)(xp + (size_t)k * XS2_STRIDE);
            ulonglong2 A1 = *(const ulonglong2*)(xp + (size_t)k * XS2_STRIDE + 4);
            ulonglong2 A2 = *(const ulonglong2*)(xp + (size_t)k * XS2_STRIDE + 8);
            ulonglong2 A3 = *(const ulonglong2*)(xp + (size_t)k * XS2_STRIDE + 12);
            // 8 codes: two contiguous 16B loads (lanes cover contiguous 256B)
            ulonglong2 B0 = *(const ulonglong2*)(ep + (size_t)k * ES_STRIDE);
            ulonglong2 B1 = *(const ulonglong2*)(ep + (size_t)k * ES_STRIDE + 64);
            unsigned long long a[8] = {A0.x, A0.y, A1.x, A1.y, A2.x, A2.y, A3.x, A3.y};
            unsigned long long b[4] = {B0.x, B0.y, B1.x, B1.y};
#pragma unroll
            for (int r = 0; r < 8; r++) {
                acc[r][0] = ffma2(a[r], b[0], acc[r][0]);
                acc[r][1] = ffma2(a[r], b[1], acc[r][1]);
                acc[r][2] = ffma2(a[r], b[2], acc[r][2]);
                acc[r][3] = ffma2(a[r], b[3], acc[r][3]);
            }
        }

        // ---- per-chunk argmax (first-max tie-break, matching jnp.argmax) ----
        float hnA0 = g_hn[c0a + 0], hnA1 = g_hn[c0a + 1];
        float hnA2 = g_hn[c0a + 2], hnA3 = g_hn[c0a + 3];
        float hnB0 = g_hn[c0b + 0], hnB1 = g_hn[c0b + 1];
        float hnB2 = g_hn[c0b + 2], hnB3 = g_hn[c0b + 3];
#pragma unroll
        for (int r = 0; r < 8; r++) {
            float bv = -3.4e38f;
            int   bi = 0;
            float v0, v1;
            unpack2(acc[r][0], v0, v1);
            v0 -= hnA0; v1 -= hnA1;
            if (v0 > bv) { bv = v0; bi = c0a + 0; }
            if (v1 > bv) { bv = v1; bi = c0a + 1; }
            unpack2(acc[r][1], v0, v1);
            v0 -= hnA2; v1 -= hnA3;
            if (v0 > bv) { bv = v0; bi = c0a + 2; }
            if (v1 > bv) { bv = v1; bi = c0a + 3; }
            unpack2(acc[r][2], v0, v1);
            v0 -= hnB0; v1 -= hnB1;
            if (v0 > bv) { bv = v0; bi = c0b + 0; }
            if (v1 > bv) { bv = v1; bi = c0b + 1; }
            unpack2(acc[r][3], v0, v1);
            v0 -= hnB2; v1 -= hnB3;
            if (v0 > bv) { bv = v0; bi = c0b + 2; }
            if (v1 > bv) { bv = v1; bi = c0b + 3; }
            // reduce across the 16 tx lanes sharing this row (half-warp)
#pragma unroll
            for (int off = 8; off > 0; off >>= 1) {
                float ov = __shfl_xor_sync(0xffffffffu, bv, off);
                int   oi = __shfl_xor_sync(0xffffffffu, bi, off);
                if (ov > bv || (ov == bv && oi < bi)) { bv = ov; bi = oi; }
            }
            if (bv > gbv[r]) { gbv[r] = bv; gbi[r] = bi; }   // earlier chunk wins ties
        }
    }

    // ---- write indices + gather quantize rows ----
#pragma unroll
    for (int r = 0; r < 8; r++) {
        int row = rowBase + ty * 8 + r;
        if (row < N) {
            if (out_ind && tx == 0) out_ind[row] = (float)gbi[r];
            if (out_q) {
                const float4* src = (const float4*)(embed + (size_t)gbi[r] * 128);
                float4* dst = (float4*)(out_q + (size_t)row * 128);
                dst[tx * 2]     = src[tx * 2];
                dst[tx * 2 + 1] = src[tx * 2 + 1];
            }
        }
    }
}

// ---------------------------------------------------------------------------
extern "C" void kernel_launch(void* const* d_in, const int* in_sizes, int n_in,
                              void* d_out, int out_size) {
    const float* x     = (const float*)d_in[0];
    const float* embed = (const float*)d_in[1];
    const int N = in_sizes[0] / 128;   // 131072
    const int K = in_sizes[1] / 128;   // 1024

    float* out     = (float*)d_out;
    float* out_ind = out;              // default: [ind (N)][quantize (N*128)]
    float* out_q   = out + N;
    long long os = (long long)out_size;
    if (os == (long long)N * 128) { out_ind = nullptr; out_q = out; }
    else if (os == (long long)N) { out_q = nullptr; }

    hn_kernel<<<(K + 127) / 128, 128>>>(embed, K);

    cudaFuncSetAttribute(vq_kernel, cudaFuncAttributeMaxDynamicSharedMemorySize,
                         SMEM_FLOATS * 4);
    dim3 blk(16, 16);
    int grid = (N + BM - 1) / BM;
    vq_kernel<<<grid, blk, SMEM_FLOATS * 4>>>(x, embed, N, K, out_ind, out_q);
}

// round 5
// speedup vs baseline: 1.6553x; 1.0589x over previous
#include <cuda_runtime.h>
#include <cuda_bf16.h>

// ===========================================================================
// EuclideanCodebook: ind = argmax_c ( x·e_c - 0.5||e_c||^2 ), q = embed[ind].
// bf16 3-term split GEMM on mma.sync.m16n8k16 (baseline PTX, no tcgen05):
//   x = xh + xl, e = eh + el ;  x·e ~= xh·eh + xl·eh + xh·el
// A = [xh|xl] (256 bf16/row), B = [eh|el] (256 bf16/code), 3 passes of K=128.
// Abs error ~2e-4; rows with top2-margin < 4e-3 exactly re-scored in fp32.
// ===========================================================================

#define NROWS   131072
#define KCODES  1024
#define MARGIN_EPS 4e-3f
#define STRIDE_B 528            // 264 bf16 per smem row (16B pad: LDSM conflict-free)

// smem byte offsets
#define S_HN    0                         // 1024 floats
#define S_A     4096                      // 128 x 528 B
#define S_B0    (S_A  + 67584)
#define S_B1    (S_B0 + 67584)
#define S_BV    (S_B1 + 67584)            // float[4][128]
#define S_V2    (S_BV + 2048)             // float[4][128]
#define S_BI    (S_V2 + 2048)             // int[4][128]
#define S_IND   (S_BI + 2048)             // int[128]
#define S_TOTAL (S_IND + 512)             // 213504 B

// __device__ scratch (allocation-free)
__device__ __align__(16) __nv_bfloat16 g_Xa[(size_t)NROWS * 256];  // [xh|xl]
__device__ __align__(16) __nv_bfloat16 g_Ea[KCODES * 256];         // [eh|el]
__device__ float g_hn[KCODES];
__device__ int   g_rcnt;
__device__ int   g_rrows[NROWS];

// ---------------------------------------------------------------------------
__device__ __forceinline__ unsigned smem_u32(const void* p) {
    unsigned a;
    asm("{ .reg .u64 t; cvta.to.shared.u64 t, %1; cvt.u32.u64 %0, t; }"
        : "=r"(a) : "l"(p));
    return a;
}

#define LDSM_X4(r, addr)                                                      \
    asm volatile("ldmatrix.sync.aligned.m8n8.x4.shared.b16 {%0,%1,%2,%3}, [%4];" \
        : "=r"((r)[0]), "=r"((r)[1]), "=r"((r)[2]), "=r"((r)[3]) : "r"(addr))

#define MMA16816(d, a, b0, b1)                                                \
    asm volatile("mma.sync.aligned.m16n8k16.row.col.f32.bf16.bf16.f32 "       \
        "{%0,%1,%2,%3}, {%4,%5,%6,%7}, {%8,%9}, {%0,%1,%2,%3};"               \
        : "+f"((d)[0]), "+f"((d)[1]), "+f"((d)[2]), "+f"((d)[3])              \
        : "r"((a)[0]), "r"((a)[1]), "r"((a)[2]), "r"((a)[3]), "r"(b0), "r"(b1))

#define CP_COMMIT() asm volatile("cp.async.commit_group;" ::: "memory")
#define CP_WAIT1()  asm volatile("cp.async.wait_group 1;" ::: "memory")

// ---------------------------------------------------------------------------
// prep kernels
// ---------------------------------------------------------------------------
__global__ void prep_e(const float* __restrict__ embed) {
    int c = blockIdx.x * blockDim.x + threadIdx.x;
    if (c == 0 && blockIdx.x == 0) g_rcnt = 0;
    if (c >= KCODES) return;
    const float* e = embed + (size_t)c * 128;
    __nv_bfloat16* o = g_Ea + (size_t)c * 256;
    float s = 0.f;
#pragma unroll 4
    for (int d = 0; d < 128; d++) {
        float v = e[d];
        s += v * v;
        __nv_bfloat16 hi = __float2bfloat16(v);
        __nv_bfloat16 lo = __float2bfloat16(v - __bfloat162float(hi));
        o[d] = hi; o[128 + d] = lo;
    }
    g_hn[c] = 0.5f * s;
}

__global__ void prep_x(const float* __restrict__ x) {
    size_t i = (size_t)blockIdx.x * blockDim.x + threadIdx.x;  // float4 index
    size_t row = i >> 5;
    int c4 = (int)(i & 31);
    float4 v = ((const float4*)x)[i];
    __nv_bfloat16 h0 = __float2bfloat16(v.x), h1 = __float2bfloat16(v.y);
    __nv_bfloat16 h2 = __float2bfloat16(v.z), h3 = __float2bfloat16(v.w);
    float l0 = v.x - __bfloat162float(h0), l1 = v.y - __bfloat162float(h1);
    float l2 = v.z - __bfloat162float(h2), l3 = v.w - __bfloat162float(h3);
    __nv_bfloat162* hd = (__nv_bfloat162*)(g_Xa + row * 256 + c4 * 4);
    hd[0] = __nv_bfloat162(h0, h1);
    hd[1] = __nv_bfloat162(h2, h3);
    __nv_bfloat162* ld = (__nv_bfloat162*)(g_Xa + row * 256 + 128 + c4 * 4);
    ld[0] = __floats2bfloat162_rn(l0, l1);
    ld[1] = __floats2bfloat162_rn(l2, l3);
}

// ---------------------------------------------------------------------------
// B chunk loader: 128 codes x 256 bf16 (512 B/code) -> smem [code][264+pad]
// ---------------------------------------------------------------------------
__device__ __forceinline__ void load_B_async(unsigned sb, int ch, int bufOff, int tid) {
    const char* src = (const char*)g_Ea + (size_t)ch * 128 * 512;
#pragma unroll
    for (int it = 0; it < 16; it++) {
        int idx = tid + it * 256;
        int r = idx >> 5, kk = idx & 31;
        unsigned dst = sb + bufOff + r * STRIDE_B + kk * 16;
        const char* s = src + r * 512 + kk * 16;
        asm volatile("cp.async.cg.shared.global [%0], [%1], 16;"
                     :: "r"(dst), "l"(s));
    }
}

// ---------------------------------------------------------------------------
// main kernel: 1024 CTAs x 256 threads; CTA = 128 rows x all 1024 codes.
// Warps: 2 (row) x 4 (code); warp tile 64 rows x 32 codes per 128-code chunk.
// ---------------------------------------------------------------------------
__global__ __launch_bounds__(256, 1)
void vq_main(const float* __restrict__ embed,
             float* __restrict__ out_ind, float* __restrict__ out_q) {
    extern __shared__ char smem[];
    unsigned sb = smem_u32(smem);
    const int tid  = threadIdx.x;
    const int lane = tid & 31, wid = tid >> 5;
    const int wr = wid & 1, wc = wid >> 1;
    const int rowBase = blockIdx.x * 128;
    float* hnS = (float*)(smem + S_HN);

    // ---- prologue: hn + A tile, kick off B chunks 0 and 1 ----
    ((float4*)hnS)[tid] = ((const float4*)g_hn)[tid];
    {
        const uint4* src = (const uint4*)(g_Xa + (size_t)rowBase * 256);
#pragma unroll
        for (int it = 0; it < 16; it++) {
            int idx = tid + it * 256;
            int r = idx >> 5, kk = idx & 31;
            *(uint4*)(smem + S_A + r * STRIDE_B + kk * 16) = src[idx];
        }
    }
    load_B_async(sb, 0, S_B0, tid); CP_COMMIT();
    load_B_async(sb, 1, S_B1, tid); CP_COMMIT();

    float bv[8], v2[8]; int bi[8];
#pragma unroll
    for (int s = 0; s < 8; s++) { bv[s] = -3.4e38f; v2[s] = -3.4e38f; bi[s] = 0; }

    // lane-dependent address pieces
    const unsigned aRowOff = (unsigned)(wr * 64 + (lane & 15)) * STRIDE_B
                             + ((lane >> 4) * 16);
    const unsigned bRowOff = (unsigned)(wc * 32 + ((lane >> 4) * 8) + (lane & 7)) * STRIDE_B
                             + (((lane >> 3) & 1) * 16);

    for (int ch = 0; ch < 8; ch++) {
        CP_WAIT1();
        __syncthreads();                       // chunk ch resident for all

        float d[4][4][4];
#pragma unroll
        for (int mt = 0; mt < 4; mt++)
#pragma unroll
            for (int nt = 0; nt < 4; nt++)
#pragma unroll
                for (int e = 0; e < 4; e++) d[mt][nt][e] = 0.f;

        const unsigned Abase = sb + S_A + aRowOff;
        const unsigned Bbase = sb + ((ch & 1) ? S_B1 : S_B0) + bRowOff;

#pragma unroll
        for (int p = 0; p < 3; p++) {
            const unsigned aK = (p == 1) ? 256u : 0u;   // bytes (xl at +128 bf16)
            const unsigned bK = (p == 2) ? 256u : 0u;   // bytes (el at +128 bf16)
#pragma unroll
            for (int kk = 0; kk < 8; kk++) {
                unsigned af[4][4];
#pragma unroll
                for (int mt = 0; mt < 4; mt++)
                    LDSM_X4(af[mt], Abase + mt * (16 * STRIDE_B) + aK + kk * 32);
                unsigned bfr[2][4];
#pragma unroll
                for (int j = 0; j < 2; j++)
                    LDSM_X4(bfr[j], Bbase + j * (16 * STRIDE_B) + bK + kk * 32);
#pragma unroll
                for (int mt = 0; mt < 4; mt++)
#pragma unroll
                    for (int nt = 0; nt < 4; nt++)
                        MMA16816(d[mt][nt], af[mt],
                                 bfr[nt >> 1][(nt & 1) * 2],
                                 bfr[nt >> 1][(nt & 1) * 2 + 1]);
            }
        }

        // ---- fold -0.5||e||^2, update per-thread running top-2 ----
        const int cb = ch * 128 + wc * 32 + (lane & 3) * 2;
#pragma unroll
        for (int mt = 0; mt < 4; mt++)
#pragma unroll
            for (int h = 0; h < 2; h++) {
                const int s = mt * 2 + h;
#pragma unroll
                for (int nt = 0; nt < 4; nt++)
#pragma unroll
                    for (int e = 0; e < 2; e++) {
                        int code = cb + nt * 8 + e;
                        float v = d[mt][nt][h * 2 + e] - hnS[code];
                        if (v > bv[s]) { v2[s] = bv[s]; bv[s] = v; bi[s] = code; }
                        else if (v > v2[s]) v2[s] = v;
                    }
            }

        __syncthreads();                       // all warps done with this buf
        if (ch + 2 < 8) { load_B_async(sb, ch + 2, (ch & 1) ? S_B1 : S_B0, tid); CP_COMMIT(); }
    }

    // ---- reduce across 4 lanes sharing each row (lane&3 varies) ----
#pragma unroll
    for (int s = 0; s < 8; s++) {
#pragma unroll
        for (int off = 1; off <= 2; off <<= 1) {
            float ov = __shfl_xor_sync(0xffffffffu, bv[s], off);
            float o2 = __shfl_xor_sync(0xffffffffu, v2[s], off);
            int   oi = __shfl_xor_sync(0xffffffffu, bi[s], off);
            float mn = fminf(bv[s], ov);
            v2[s] = fmaxf(fmaxf(v2[s], o2), mn);
            if (ov > bv[s] || (ov == bv[s] && oi < bi[s])) { bv[s] = ov; bi[s] = oi; }
        }
    }
    if ((lane & 3) == 0) {
#pragma unroll
        for (int s = 0; s < 8; s++) {
            int mt = s >> 1, h = s & 1;
            int r = wr * 64 + mt * 16 + h * 8 + (lane >> 2);
            ((float*)(smem + S_BV))[wc * 128 + r] = bv[s];
            ((float*)(smem + S_V2))[wc * 128 + r] = v2[s];
            ((int*)(smem + S_BI))[wc * 128 + r]   = bi[s];
        }
    }
    __syncthreads();

    // ---- merge 4 code-warp strips, write ind, flag small margins ----
    if (tid < 128) {
        float B = -3.4e38f, S2 = -3.4e38f; int I = 0;
#pragma unroll
        for (int w = 0; w < 4; w++) {
            float ov = ((const float*)(smem + S_BV))[w * 128 + tid];
            float o2 = ((const float*)(smem + S_V2))[w * 128 + tid];
            int   oi = ((const int*)(smem + S_BI))[w * 128 + tid];
            float mn = fminf(B, ov);
            S2 = fmaxf(fmaxf(S2, o2), mn);
            if (ov > B || (ov == B && oi < I)) { B = ov; I = oi; }
        }
        int row = rowBase + tid;
        if (out_ind) out_ind[row] = (float)I;
        if (B - S2 < MARGIN_EPS) {
            int s = atomicAdd(&g_rcnt, 1);
            if (s < NROWS) g_rrows[s] = row;
        }
        ((int*)(smem + S_IND))[tid] = I;
    }
    __syncthreads();

    // ---- cooperative gather of quantize rows ----
    if (out_q) {
        const int* inds = (const int*)(smem + S_IND);
        for (int i = tid; i < 128 * 32; i += 256) {
            int r = i >> 5, c4 = i & 31;
            float4 v = ((const float4*)(embed + (size_t)inds[r] * 128))[c4];
            ((float4*)(out_q + (size_t)(rowBase + r) * 128))[c4] = v;
        }
    }
}

// ---------------------------------------------------------------------------
// rescue: exact fp32 re-score for small-margin rows
// ---------------------------------------------------------------------------
__global__ void rescue_kernel(const float* __restrict__ x,
                              const float* __restrict__ embed,
                              float* __restrict__ out_ind,
                              float* __restrict__ out_q) {
    __shared__ float xs[128];
    __shared__ float bvs[128];
    __shared__ int   bis[128];
    const int tid = threadIdx.x;
    const int cnt = g_rcnt < NROWS ? g_rcnt : NROWS;

    for (int it = blockIdx.x; it < cnt; it += gridDim.x) {
        int row = g_rrows[it];
        if (tid < 128) xs[tid] = x[(size_t)row * 128 + tid];
        __syncthreads();

        float bv = -3.4e38f;
        int bi = 0;
#pragma unroll
        for (int j = 0; j < 8; j++) {
            int c = tid * 8 + j;
            const float* e = embed + (size_t)c * 128;
            float s = 0.f;
#pragma unroll 8
            for (int d = 0; d < 128; d++) s = fmaf(xs[d], e[d], s);
            s -= g_hn[c];
            if (s > bv) { bv = s; bi = c; }
        }
        bvs[tid] = bv; bis[tid] = bi;
        __syncthreads();
#pragma unroll
        for (int st = 64; st > 0; st >>= 1) {
            if (tid < st) {
                float ov = bvs[tid + st]; int oi = bis[tid + st];
                if (ov > bvs[tid] || (ov == bvs[tid] && oi < bis[tid])) {
                    bvs[tid] = ov; bis[tid] = oi;
                }
            }
            __syncthreads();
        }
        int fi = bis[0];
        if (tid == 0 && out_ind) out_ind[row] = (float)fi;
        if (out_q && tid < 128)
            out_q[(size_t)row * 128 + tid] = embed[(size_t)fi * 128 + tid];
        __syncthreads();
    }
}

// ---------------------------------------------------------------------------
extern "C" void kernel_launch(void* const* d_in, const int* in_sizes, int n_in,
                              void* d_out, int out_size) {
    const float* x     = (const float*)d_in[0];
    const float* embed = (const float*)d_in[1];
    const int N = in_sizes[0] / 128;   // 131072

    float* out     = (float*)d_out;
    float* out_ind = out;              // layout: [ind (N)][quantize (N*128)]
    float* out_q   = out + N;
    long long os = (long long)out_size;
    if (os == (long long)N * 128) { out_ind = nullptr; out_q = out; }
    else if (os == (long long)N)  { out_q = nullptr; }

    prep_e<<<(KCODES + 127) / 128, 128>>>(embed);
    prep_x<<<(N * 128) / (4 * 256), 256>>>(x);

    cudaFuncSetAttribute(vq_main, cudaFuncAttributeMaxDynamicSharedMemorySize,
                         S_TOTAL);
    vq_main<<<N / 128, 256, S_TOTAL>>>(embed, out_ind, out_q);

    rescue_kernel<<<256, 128>>>(x, embed, out_ind, out_q);
}

// round 6
// speedup vs baseline: 3.1476x; 1.9015x over previous
#include <cuda_runtime.h>
#include <cuda_bf16.h>

// ===========================================================================
// EuclideanCodebook: ind = argmax_c ( x·e_c - 0.5||e_c||^2 ), q = embed[ind].
// bf16 3-term split GEMM on mma.sync.m16n8k16:
//   x = xh + xl, e = eh + el ;  x·e ~= xh·eh + xl·eh + xh·el
// R6: interleaved passes (share LDSM frags across the 3 terms), x-split fused
// into the main kernel prologue (no prep_x / g_Xa), efficient rescue.
// ===========================================================================

#define NROWS   131072
#define KCODES  1024
#define MARGIN_EPS 1.5e-3f
#define STRIDE_B 528            // 264 bf16 per smem row (16B pad: LDSM conflict-free)

// smem byte offsets
#define S_HN    0                         // 1024 floats
#define S_A     4096                      // 128 x 528 B  [xh(256B)|xl(256B)|pad]
#define S_B0    (S_A  + 67584)
#define S_B1    (S_B0 + 67584)            // [eh(256B)|el(256B)|pad] per code
#define S_BV    (S_B1 + 67584)            // float[4][128]
#define S_V2    (S_BV + 2048)             // float[4][128]
#define S_BI    (S_V2 + 2048)             // int[4][128]
#define S_IND   (S_BI + 2048)             // int[128]
#define S_TOTAL (S_IND + 512)             // 213504 B

// __device__ scratch (allocation-free)
__device__ __align__(16) __nv_bfloat16 g_Ea[KCODES * 256];   // [eh|el]
__device__ float g_hn[KCODES];
__device__ int   g_rcnt;
__device__ int   g_rrows[NROWS];

// ---------------------------------------------------------------------------
__device__ __forceinline__ unsigned smem_u32(const void* p) {
    unsigned a;
    asm("{ .reg .u64 t; cvta.to.shared.u64 t, %1; cvt.u32.u64 %0, t; }"
        : "=r"(a) : "l"(p));
    return a;
}

#define LDSM_X4(r, addr)                                                      \
    asm volatile("ldmatrix.sync.aligned.m8n8.x4.shared.b16 {%0,%1,%2,%3}, [%4];" \
        : "=r"((r)[0]), "=r"((r)[1]), "=r"((r)[2]), "=r"((r)[3]) : "r"(addr))

#define MMA16816(d, a, b0, b1)                                                \
    asm volatile("mma.sync.aligned.m16n8k16.row.col.f32.bf16.bf16.f32 "       \
        "{%0,%1,%2,%3}, {%4,%5,%6,%7}, {%8,%9}, {%0,%1,%2,%3};"               \
        : "+f"((d)[0]), "+f"((d)[1]), "+f"((d)[2]), "+f"((d)[3])              \
        : "r"((a)[0]), "r"((a)[1]), "r"((a)[2]), "r"((a)[3]), "r"(b0), "r"(b1))

#define CP_COMMIT() asm volatile("cp.async.commit_group;" ::: "memory")
#define CP_WAIT1()  asm volatile("cp.async.wait_group 1;" ::: "memory")

__device__ __forceinline__ unsigned pack_bf16x2(float a, float b) {
    __nv_bfloat162 h = __floats2bfloat162_rn(a, b);
    return *(unsigned*)&h;
}

// ---------------------------------------------------------------------------
__global__ void prep_e(const float* __restrict__ embed) {
    int c = blockIdx.x * blockDim.x + threadIdx.x;
    if (c == 0 && blockIdx.x == 0) g_rcnt = 0;
    if (c >= KCODES) return;
    const float* e = embed + (size_t)c * 128;
    __nv_bfloat16* o = g_Ea + (size_t)c * 256;
    float s = 0.f;
#pragma unroll 4
    for (int d = 0; d < 128; d++) {
        float v = e[d];
        s += v * v;
        __nv_bfloat16 hi = __float2bfloat16(v);
        __nv_bfloat16 lo = __float2bfloat16(v - __bfloat162float(hi));
        o[d] = hi; o[128 + d] = lo;
    }
    g_hn[c] = 0.5f * s;
}

// ---------------------------------------------------------------------------
__device__ __forceinline__ void load_B_async(unsigned sb, int ch, int bufOff, int tid) {
    const char* src = (const char*)g_Ea + (size_t)ch * 128 * 512;
#pragma unroll
    for (int it = 0; it < 16; it++) {
        int idx = tid + it * 256;
        int r = idx >> 5, kk = idx & 31;
        unsigned dst = sb + bufOff + r * STRIDE_B + kk * 16;
        const char* s = src + r * 512 + kk * 16;
        asm volatile("cp.async.cg.shared.global [%0], [%1], 16;"
                     :: "r"(dst), "l"(s));
    }
}

// ---------------------------------------------------------------------------
// main: 1024 CTAs x 256 threads; CTA = 128 rows x 1024 codes (8 chunks x 128).
// Warps 2(row) x 4(code); warp tile 64 x 32. Three split-terms interleaved
// per k-step so A/B fragments are loaded once and used by 3 MMA groups.
// ---------------------------------------------------------------------------
__global__ __launch_bounds__(256, 1)
void vq_main(const float* __restrict__ x, const float* __restrict__ embed,
             float* __restrict__ out_ind, float* __restrict__ out_q) {
    extern __shared__ char smem[];
    unsigned sb = smem_u32(smem);
    const int tid  = threadIdx.x;
    const int lane = tid & 31, wid = tid >> 5;
    const int wr = wid & 1, wc = wid >> 1;
    const int rowBase = blockIdx.x * 128;
    float* hnS = (float*)(smem + S_HN);

    // ---- prologue: hn + fused x->bf16-split A tile; kick B chunks 0,1 ----
    ((float4*)hnS)[tid] = ((const float4*)g_hn)[tid];
    {
        const float4* src = (const float4*)(x + (size_t)rowBase * 128);
#pragma unroll
        for (int it = 0; it < 16; it++) {
            int idx = tid + it * 256;
            int r = idx >> 5, kk = idx & 31;
            float4 v = src[idx];
            __nv_bfloat16 h0 = __float2bfloat16(v.x), h1 = __float2bfloat16(v.y);
            __nv_bfloat16 h2 = __float2bfloat16(v.z), h3 = __float2bfloat16(v.w);
            uint2 hi, lo;
            { __nv_bfloat162 t0(h0, h1), t1(h2, h3);
              hi.x = *(unsigned*)&t0; hi.y = *(unsigned*)&t1; }
            lo.x = pack_bf16x2(v.x - __bfloat162float(h0), v.y - __bfloat162float(h1));
            lo.y = pack_bf16x2(v.z - __bfloat162float(h2), v.w - __bfloat162float(h3));
            *(uint2*)(smem + S_A + r * STRIDE_B + kk * 8)       = hi;
            *(uint2*)(smem + S_A + r * STRIDE_B + 256 + kk * 8) = lo;
        }
    }
    load_B_async(sb, 0, S_B0, tid); CP_COMMIT();
    load_B_async(sb, 1, S_B1, tid); CP_COMMIT();

    float bv[8], v2[8]; int bi[8];
#pragma unroll
    for (int s = 0; s < 8; s++) { bv[s] = -3.4e38f; v2[s] = -3.4e38f; bi[s] = 0; }

    const unsigned aRowOff = (unsigned)(wr * 64 + (lane & 15)) * STRIDE_B
                             + ((lane >> 4) * 16);
    const unsigned bRowOff = (unsigned)(wc * 32 + ((lane >> 4) * 8) + (lane & 7)) * STRIDE_B
                             + (((lane >> 3) & 1) * 16);

    for (int ch = 0; ch < 8; ch++) {
        CP_WAIT1();
        __syncthreads();                       // chunk ch resident

        float d[4][4][4];
#pragma unroll
        for (int mt = 0; mt < 4; mt++)
#pragma unroll
            for (int nt = 0; nt < 4; nt++)
#pragma unroll
                for (int e = 0; e < 4; e++) d[mt][nt][e] = 0.f;

        const unsigned Abase = sb + S_A + aRowOff;
        const unsigned Bbase = sb + ((ch & 1) ? S_B1 : S_B0) + bRowOff;

#pragma unroll
        for (int kk = 0; kk < 8; kk++) {
            unsigned ah[4][4], al[4][4];
#pragma unroll
            for (int mt = 0; mt < 4; mt++) {
                LDSM_X4(ah[mt], Abase + mt * (16 * STRIDE_B) + kk * 32);
                LDSM_X4(al[mt], Abase + mt * (16 * STRIDE_B) + 256 + kk * 32);
            }
            unsigned bh[2][4], bl[2][4];
#pragma unroll
            for (int j = 0; j < 2; j++) {
                LDSM_X4(bh[j], Bbase + j * (16 * STRIDE_B) + kk * 32);
                LDSM_X4(bl[j], Bbase + j * (16 * STRIDE_B) + 256 + kk * 32);
            }
#pragma unroll
            for (int mt = 0; mt < 4; mt++)
#pragma unroll
                for (int nt = 0; nt < 4; nt++) {
                    unsigned b0h = bh[nt >> 1][(nt & 1) * 2];
                    unsigned b1h = bh[nt >> 1][(nt & 1) * 2 + 1];
                    unsigned b0l = bl[nt >> 1][(nt & 1) * 2];
                    unsigned b1l = bl[nt >> 1][(nt & 1) * 2 + 1];
                    MMA16816(d[mt][nt], ah[mt], b0h, b1h);   // xh·eh
                    MMA16816(d[mt][nt], al[mt], b0h, b1h);   // xl·eh
                    MMA16816(d[mt][nt], ah[mt], b0l, b1l);   // xh·el
                }
        }

        // ---- fold -0.5||e||^2, update per-thread running top-2 ----
        const int cb = ch * 128 + wc * 32 + (lane & 3) * 2;
#pragma unroll
        for (int mt = 0; mt < 4; mt++)
#pragma unroll
            for (int h = 0; h < 2; h++) {
                const int s = mt * 2 + h;
#pragma unroll
                for (int nt = 0; nt < 4; nt++)
#pragma unroll
                    for (int e = 0; e < 2; e++) {
                        int code = cb + nt * 8 + e;
                        float v = d[mt][nt][h * 2 + e] - hnS[code];
                        if (v > bv[s]) { v2[s] = bv[s]; bv[s] = v; bi[s] = code; }
                        else if (v > v2[s]) v2[s] = v;
                    }
            }

        __syncthreads();
        if (ch + 2 < 8) { load_B_async(sb, ch + 2, (ch & 1) ? S_B1 : S_B0, tid); CP_COMMIT(); }
    }

    // ---- reduce across 4 lanes sharing each row ----
#pragma unroll
    for (int s = 0; s < 8; s++) {
#pragma unroll
        for (int off = 1; off <= 2; off <<= 1) {
            float ov = __shfl_xor_sync(0xffffffffu, bv[s], off);
            float o2 = __shfl_xor_sync(0xffffffffu, v2[s], off);
            int   oi = __shfl_xor_sync(0xffffffffu, bi[s], off);
            float mn = fminf(bv[s], ov);
            v2[s] = fmaxf(fmaxf(v2[s], o2), mn);
            if (ov > bv[s] || (ov == bv[s] && oi < bi[s])) { bv[s] = ov; bi[s] = oi; }
        }
    }
    if ((lane & 3) == 0) {
#pragma unroll
        for (int s = 0; s < 8; s++) {
            int mt = s >> 1, h = s & 1;
            int r = wr * 64 + mt * 16 + h * 8 + (lane >> 2);
            ((float*)(smem + S_BV))[wc * 128 + r] = bv[s];
            ((float*)(smem + S_V2))[wc * 128 + r] = v2[s];
            ((int*)(smem + S_BI))[wc * 128 + r]   = bi[s];
        }
    }
    __syncthreads();

    // ---- merge 4 code-warp strips, write ind, flag small margins ----
    if (tid < 128) {
        float B = -3.4e38f, S2 = -3.4e38f; int I = 0;
#pragma unroll
        for (int w = 0; w < 4; w++) {
            float ov = ((const float*)(smem + S_BV))[w * 128 + tid];
            float o2 = ((const float*)(smem + S_V2))[w * 128 + tid];
            int   oi = ((const int*)(smem + S_BI))[w * 128 + tid];
            float mn = fminf(B, ov);
            S2 = fmaxf(fmaxf(S2, o2), mn);
            if (ov > B || (ov == B && oi < I)) { B = ov; I = oi; }
        }
        int row = rowBase + tid;
        if (out_ind) out_ind[row] = (float)I;
        if (B - S2 < MARGIN_EPS) {
            int s = atomicAdd(&g_rcnt, 1);
            if (s < NROWS) g_rrows[s] = row;
        }
        ((int*)(smem + S_IND))[tid] = I;
    }
    __syncthreads();

    // ---- cooperative gather of quantize rows ----
    if (out_q) {
        const int* inds = (const int*)(smem + S_IND);
        for (int i = tid; i < 128 * 32; i += 256) {
            int r = i >> 5, c4 = i & 31;
            float4 v = ((const float4*)(embed + (size_t)inds[r] * 128))[c4];
            ((float4*)(out_q + (size_t)(rowBase + r) * 128))[c4] = v;
        }
    }
}

// ---------------------------------------------------------------------------
// rescue: exact fp32 re-score for small-margin rows. Block per row, 256 thr,
// 4 codes/thread, float4 ILP.
// ---------------------------------------------------------------------------
__global__ __launch_bounds__(256, 4)
void rescue_kernel(const float* __restrict__ x,
                   const float* __restrict__ embed,
                   float* __restrict__ out_ind,
                   float* __restrict__ out_q) {
    __shared__ float4 xs4[32];
    __shared__ float bvs[256];
    __shared__ int   bis[256];
    const int tid = threadIdx.x;
    const int cnt = g_rcnt < NROWS ? g_rcnt : NROWS;

    for (int it = blockIdx.x; it < cnt; it += gridDim.x) {
        int row = g_rrows[it];
        if (tid < 32) xs4[tid] = ((const float4*)(x + (size_t)row * 128))[tid];
        __syncthreads();

        float bv = -3.4e38f;
        int   bi = 0;
#pragma unroll
        for (int j = 0; j < 4; j++) {
            int c = j * 256 + tid;
            const float4* e4 = (const float4*)(embed + (size_t)c * 128);
            float s0 = 0.f, s1 = 0.f, s2 = 0.f, s3 = 0.f;
#pragma unroll
            for (int i = 0; i < 8; i++) {
                float4 xa = xs4[i * 4 + 0], ea = e4[i * 4 + 0];
                float4 xb = xs4[i * 4 + 1], eb = e4[i * 4 + 1];
                float4 xc = xs4[i * 4 + 2], ec = e4[i * 4 + 2];
                float4 xd = xs4[i * 4 + 3], ed = e4[i * 4 + 3];
                s0 = fmaf(xa.x, ea.x, fmaf(xa.y, ea.y, fmaf(xa.z, ea.z, fmaf(xa.w, ea.w, s0))));
                s1 = fmaf(xb.x, eb.x, fmaf(xb.y, eb.y, fmaf(xb.z, eb.z, fmaf(xb.w, eb.w, s1))));
                s2 = fmaf(xc.x, ec.x, fmaf(xc.y, ec.y, fmaf(xc.z, ec.z, fmaf(xc.w, ec.w, s2))));
                s3 = fmaf(xd.x, ed.x, fmaf(xd.y, ed.y, fmaf(xd.z, ed.z, fmaf(xd.w, ed.w, s3))));
            }
            float s = (s0 + s1) + (s2 + s3) - g_hn[c];
            if (s > bv) { bv = s; bi = c; }
        }
        bvs[tid] = bv; bis[tid] = bi;
        __syncthreads();
#pragma unroll
        for (int st = 128; st > 0; st >>= 1) {
            if (tid < st) {
                float ov = bvs[tid + st]; int oi = bis[tid + st];
                if (ov > bvs[tid] || (ov == bvs[tid] && oi < bis[tid])) {
                    bvs[tid] = ov; bis[tid] = oi;
                }
            }
            __syncthreads();
        }
        int fi = bis[0];
        if (tid == 0 && out_ind) out_ind[row] = (float)fi;
        if (out_q && tid < 32)
            ((float4*)(out_q + (size_t)row * 128))[tid] =
                ((const float4*)(embed + (size_t)fi * 128))[tid];
        __syncthreads();
    }
}

// ---------------------------------------------------------------------------
extern "C" void kernel_launch(void* const* d_in, const int* in_sizes, int n_in,
                              void* d_out, int out_size) {
    const float* x     = (const float*)d_in[0];
    const float* embed = (const float*)d_in[1];
    const int N = in_sizes[0] / 128;   // 131072

    float* out     = (float*)d_out;
    float* out_ind = out;              // layout: [ind (N)][quantize (N*128)]
    float* out_q   = out + N;
    long long os = (long long)out_size;
    if (os == (long long)N * 128) { out_ind = nullptr; out_q = out; }
    else if (os == (long long)N)  { out_q = nullptr; }

    prep_e<<<(KCODES + 127) / 128, 128>>>(embed);

    cudaFuncSetAttribute(vq_main, cudaFuncAttributeMaxDynamicSharedMemorySize,
                         S_TOTAL);
    vq_main<<<N / 128, 256, S_TOTAL>>>(x, embed, out_ind, out_q);

    rescue_kernel<<<512, 256>>>(x, embed, out_ind, out_q);
}